// round 15
// baseline (speedup 1.0000x reference)
#include <cuda_runtime.h>
#include <cuda_bf16.h>

// ---------------------------------------------------------------------------
// ParallelTransportAttention  (B=2, S=256, D=512, H=8, Dh=64, df=32, rank=8)
// Round 15: R14 (297.3us) + ONE change: hol epilogue reads own-tile factors
//   from live acc registers; transpose factors via 8 conflict-free LDS.128.
//   Cuts epilogue crossbar wavefronts ~64-100 -> 32 per pair.
// ---------------------------------------------------------------------------

__device__ __align__(256) float g_scratch[3411968];

#define PAD 36

// ---------------- packed f32x2 helpers --------------------------------------
__device__ __forceinline__ unsigned long long pk2(float x, float y) {
    unsigned long long r;
    asm("mov.b64 %0, {%1,%2};" : "=l"(r) : "f"(x), "f"(y));
    return r;
}
__device__ __forceinline__ void fma2(unsigned long long& d,
                                     unsigned long long a, unsigned long long b) {
    asm("fma.rn.f32x2 %0, %1, %2, %0;" : "+l"(d) : "l"(a), "l"(b));
}
__device__ __forceinline__ float2 upk2(unsigned long long v) {
    float2 f;
    asm("mov.b64 {%0,%1}, %2;" : "=f"(f.x), "=f"(f.y) : "l"(v));
    return f;
}

// ---------------- warp-tiled 32x32x32 matmuls -------------------------------
__device__ __forceinline__ void wtile_tn(const float (*A)[PAD], const float (*B)[PAD],
                                         unsigned long long acc[4][4], int rg, int cg) {
#pragma unroll
    for (int k = 0; k < 32; k++) {
        float4 av = *(const float4*)&A[k][4 * rg];
        ulonglong2 b01 = *(const ulonglong2*)&B[k][8 * cg];
        ulonglong2 b23 = *(const ulonglong2*)&B[k][8 * cg + 4];
        unsigned long long a0 = pk2(av.x, av.x);
        unsigned long long a1 = pk2(av.y, av.y);
        unsigned long long a2 = pk2(av.z, av.z);
        unsigned long long a3 = pk2(av.w, av.w);
        fma2(acc[0][0], a0, b01.x); fma2(acc[0][1], a0, b01.y);
        fma2(acc[0][2], a0, b23.x); fma2(acc[0][3], a0, b23.y);
        fma2(acc[1][0], a1, b01.x); fma2(acc[1][1], a1, b01.y);
        fma2(acc[1][2], a1, b23.x); fma2(acc[1][3], a1, b23.y);
        fma2(acc[2][0], a2, b01.x); fma2(acc[2][1], a2, b01.y);
        fma2(acc[2][2], a2, b23.x); fma2(acc[2][3], a2, b23.y);
        fma2(acc[3][0], a3, b01.x); fma2(acc[3][1], a3, b01.y);
        fma2(acc[3][2], a3, b23.x); fma2(acc[3][3], a3, b23.y);
    }
}

__device__ __forceinline__ void wtile_nn(const float (*A)[PAD], const float (*B)[PAD],
                                         unsigned long long acc[4][4], int rg, int cg) {
#pragma unroll
    for (int k0 = 0; k0 < 32; k0 += 4) {
        float4 ar0 = *(const float4*)&A[4 * rg + 0][k0];
        float4 ar1 = *(const float4*)&A[4 * rg + 1][k0];
        float4 ar2 = *(const float4*)&A[4 * rg + 2][k0];
        float4 ar3 = *(const float4*)&A[4 * rg + 3][k0];
        const float* a0f = (const float*)&ar0;
        const float* a1f = (const float*)&ar1;
        const float* a2f = (const float*)&ar2;
        const float* a3f = (const float*)&ar3;
#pragma unroll
        for (int kk = 0; kk < 4; kk++) {
            ulonglong2 b01 = *(const ulonglong2*)&B[k0 + kk][8 * cg];
            ulonglong2 b23 = *(const ulonglong2*)&B[k0 + kk][8 * cg + 4];
            unsigned long long a0 = pk2(a0f[kk], a0f[kk]);
            unsigned long long a1 = pk2(a1f[kk], a1f[kk]);
            unsigned long long a2 = pk2(a2f[kk], a2f[kk]);
            unsigned long long a3 = pk2(a3f[kk], a3f[kk]);
            fma2(acc[0][0], a0, b01.x); fma2(acc[0][1], a0, b01.y);
            fma2(acc[0][2], a0, b23.x); fma2(acc[0][3], a0, b23.y);
            fma2(acc[1][0], a1, b01.x); fma2(acc[1][1], a1, b01.y);
            fma2(acc[1][2], a1, b23.x); fma2(acc[1][3], a1, b23.y);
            fma2(acc[2][0], a2, b01.x); fma2(acc[2][1], a2, b01.y);
            fma2(acc[2][2], a2, b23.x); fma2(acc[2][3], a2, b23.y);
            fma2(acc[3][0], a3, b01.x); fma2(acc[3][1], a3, b01.y);
            fma2(acc[3][2], a3, b23.x); fma2(acc[3][3], a3, b23.y);
        }
    }
}

__device__ __forceinline__ void wtile_store(float (*C)[PAD],
                                            const unsigned long long acc[4][4],
                                            int rg, int cg) {
#pragma unroll
    for (int d = 0; d < 4; d++) {
        ulonglong2 v0; v0.x = acc[d][0]; v0.y = acc[d][1];
        ulonglong2 v1; v1.x = acc[d][2]; v1.y = acc[d][3];
        *(ulonglong2*)&C[4 * rg + d][8 * cg]     = v0;
        *(ulonglong2*)&C[4 * rg + d][8 * cg + 4] = v1;
    }
}

// ================= double-buffered 64x64 GEMM tile (device fn) ==============
__device__ __forceinline__ void gemm_tile(
    const float* __restrict__ A, const float* __restrict__ B,
    const float* __restrict__ bias, float* __restrict__ C,
    int K, int lda, int ldb, int ldc, int row0, int col0,
    float (*As)[32][68], float (*Bs)[32][68])
{
    int t  = threadIdx.x;
    int tx = t & 15, ty = t >> 4;
    const float* Atile = A + (long)row0 * lda;
    const float* Btile = B + col0;
    int NC = K >> 5;

    unsigned long long acc2[4][2] = {};
    int arow = t >> 2, acol = (t & 3) * 8;
    int brow = t >> 3, bcol = (t & 7) * 8;

    float4 a0 = *(const float4*)(Atile + (long)arow * lda + acol);
    float4 a1 = *(const float4*)(Atile + (long)arow * lda + acol + 4);
    float4 b0 = *(const float4*)(Btile + (long)brow * ldb + bcol);
    float4 b1 = *(const float4*)(Btile + (long)brow * ldb + bcol + 4);
    As[0][acol+0][arow]=a0.x; As[0][acol+1][arow]=a0.y;
    As[0][acol+2][arow]=a0.z; As[0][acol+3][arow]=a0.w;
    As[0][acol+4][arow]=a1.x; As[0][acol+5][arow]=a1.y;
    As[0][acol+6][arow]=a1.z; As[0][acol+7][arow]=a1.w;
    *(float4*)&Bs[0][brow][bcol]   = b0;
    *(float4*)&Bs[0][brow][bcol+4] = b1;
    __syncthreads();
    for (int c = 0; c < NC; c++) {
        int cur = c & 1;
        if (c + 1 < NC) {
            const float* Ap = Atile + (c + 1) * 32;
            const float* Bp = Btile + (long)(c + 1) * 32 * ldb;
            a0 = *(const float4*)(Ap + (long)arow * lda + acol);
            a1 = *(const float4*)(Ap + (long)arow * lda + acol + 4);
            b0 = *(const float4*)(Bp + (long)brow * ldb + bcol);
            b1 = *(const float4*)(Bp + (long)brow * ldb + bcol + 4);
        }
#pragma unroll
        for (int k = 0; k < 32; k++) {
            float4 a4 = *(const float4*)&As[cur][k][ty * 4];
            ulonglong2 bu = *(const ulonglong2*)&Bs[cur][k][tx * 4];
            unsigned long long d0 = pk2(a4.x, a4.x);
            unsigned long long d1 = pk2(a4.y, a4.y);
            unsigned long long d2 = pk2(a4.z, a4.z);
            unsigned long long d3 = pk2(a4.w, a4.w);
            fma2(acc2[0][0], d0, bu.x); fma2(acc2[0][1], d0, bu.y);
            fma2(acc2[1][0], d1, bu.x); fma2(acc2[1][1], d1, bu.y);
            fma2(acc2[2][0], d2, bu.x); fma2(acc2[2][1], d2, bu.y);
            fma2(acc2[3][0], d3, bu.x); fma2(acc2[3][1], d3, bu.y);
        }
        if (c + 1 < NC) {
            int nxt = cur ^ 1;
            As[nxt][acol+0][arow]=a0.x; As[nxt][acol+1][arow]=a0.y;
            As[nxt][acol+2][arow]=a0.z; As[nxt][acol+3][arow]=a0.w;
            As[nxt][acol+4][arow]=a1.x; As[nxt][acol+5][arow]=a1.y;
            As[nxt][acol+6][arow]=a1.z; As[nxt][acol+7][arow]=a1.w;
            *(float4*)&Bs[nxt][brow][bcol]   = b0;
            *(float4*)&Bs[nxt][brow][bcol+4] = b1;
        }
        __syncthreads();
    }

    float bv4[4] = {0.f, 0.f, 0.f, 0.f};
    if (bias) {
#pragma unroll
        for (int j = 0; j < 4; j++) bv4[j] = bias[col0 + tx * 4 + j];
    }
#pragma unroll
    for (int ii = 0; ii < 4; ii++) {
        float2 e0 = upk2(acc2[ii][0]);
        float2 e1 = upk2(acc2[ii][1]);
        float4 o;
        o.x = e0.x + bv4[0]; o.y = e0.y + bv4[1];
        o.z = e1.x + bv4[2]; o.w = e1.y + bv4[3];
        *(float4*)(C + (long)(row0 + ty * 4 + ii) * ldc + col0 + tx * 4) = o;
    }
}

// ======================= 1) expm + M (warp-per-matrix) ======================
__global__ __launch_bounds__(64) void expm_kernel(
    const float* __restrict__ conn, const float* __restrict__ gen,
    float* __restrict__ Mout)
{
    __shared__ float sA[2][32][PAD], sP[2][32][PAD], sT[2][32][PAD];
    int t = threadIdx.x;
    int w = t >> 5, lane = t & 31;
    int rg = lane >> 2, cg = lane & 3;
    int zs = blockIdx.x * 2 + w;

    float c8[8];
#pragma unroll
    for (int r = 0; r < 8; r++) c8[r] = conn[zs * 8 + r];

    float atile[4][8];
#pragma unroll
    for (int d = 0; d < 4; d++) {
        int row = 4 * rg + d;
#pragma unroll
        for (int h = 0; h < 2; h++) {
            float4 v = make_float4(0.f, 0.f, 0.f, 0.f);
#pragma unroll
            for (int r = 0; r < 8; r++) {
                float4 g = *(const float4*)(gen + r * 1024 + row * 32 + 8 * cg + 4 * h);
                v.x += c8[r] * g.x; v.y += c8[r] * g.y;
                v.z += c8[r] * g.z; v.w += c8[r] * g.w;
            }
            atile[d][4*h+0] = v.x * 0.1f; atile[d][4*h+1] = v.y * 0.1f;
            atile[d][4*h+2] = v.z * 0.1f; atile[d][4*h+3] = v.w * 0.1f;
        }
#pragma unroll
        for (int e = 0; e < 8; e++) sA[w][row][8 * cg + e] = atile[d][e];
    }
    __syncwarp();

    float cs = 0.f;
#pragma unroll
    for (int a = 0; a < 32; a++) cs += fabsf(sA[w][a][lane]);
    float nrm = cs;
#pragma unroll
    for (int o = 16; o; o >>= 1) nrm = fmaxf(nrm, __shfl_xor_sync(0xffffffffu, nrm, o));
    int s = 0;
    while (nrm > 0.25f * ldexpf(1.f, s) && s < 12) s++;
    float sc = ldexpf(1.f, -s);

    float treg[4][8];
#pragma unroll
    for (int d = 0; d < 4; d++) {
        int row = 4 * rg + d;
#pragma unroll
        for (int e = 0; e < 8; e++) {
            float a = atile[d][e] * sc;
            sA[w][row][8 * cg + e] = a;
            sP[w][row][8 * cg + e] = a;
            treg[d][e] = a + ((row == 8 * cg + e) ? 1.f : 0.f);
        }
    }
    __syncwarp();

    for (int k = 2; k <= 9; k++) {
        unsigned long long acc[4][4] = {};
        wtile_nn(sP[w], sA[w], acc, rg, cg);
        float inv = 1.f / (float)k;
        __syncwarp();
#pragma unroll
        for (int d = 0; d < 4; d++) {
#pragma unroll
            for (int e = 0; e < 4; e++) {
                float2 f = upk2(acc[d][e]);
                float t0 = f.x * inv, t1 = f.y * inv;
                sP[w][4 * rg + d][8 * cg + 2 * e]     = t0;
                sP[w][4 * rg + d][8 * cg + 2 * e + 1] = t1;
                treg[d][2 * e]     += t0;
                treg[d][2 * e + 1] += t1;
            }
        }
        __syncwarp();
    }
#pragma unroll
    for (int d = 0; d < 4; d++)
#pragma unroll
        for (int e = 0; e < 8; e++)
            sT[w][4 * rg + d][8 * cg + e] = treg[d][e];
    __syncwarp();

    for (int it = 0; it < s; it++) {
        unsigned long long acc[4][4] = {};
        wtile_nn(sT[w], sT[w], acc, rg, cg);
        __syncwarp();
        wtile_store(sT[w], acc, rg, cg);
        __syncwarp();
    }

    unsigned long long acc[4][4] = {};
    wtile_tn(sT[w], sT[w], acc, rg, cg);
    float* mo = Mout + (size_t)zs * 1024;
#pragma unroll
    for (int d = 0; d < 4; d++) {
        float2 f0 = upk2(acc[d][0]);
        float2 f1 = upk2(acc[d][1]);
        float2 f2 = upk2(acc[d][2]);
        float2 f3 = upk2(acc[d][3]);
        float4 o0 = make_float4(f0.x, f0.y, f1.x, f1.y);
        float4 o1 = make_float4(f2.x, f2.y, f3.x, f3.y);
        *(float4*)(mo + (4 * rg + d) * 32 + 8 * cg)     = o0;
        *(float4*)(mo + (4 * rg + d) * 32 + 8 * cg + 4) = o1;
    }
}

// ============= 2+3) fused: QKV GEMMs (blocks 0..191) + holonomy =============
// hol: block = (z, i, 8-wide j tile); warp w -> j = jt*8+w; P stored over Mj.
// __launch_bounds__(256, 4): 64-reg cap -> 4 CTAs/SM (validated R14 win).
__global__ __launch_bounds__(256, 4) void hol_qkv_kernel(
    const float* __restrict__ Mg, float* __restrict__ hol,
    const float* __restrict__ base,
    const float* __restrict__ Wq, const float* __restrict__ Wk, const float* __restrict__ Wv,
    const float* __restrict__ bq, const float* __restrict__ bk, const float* __restrict__ bv,
    float* __restrict__ Qo, float* __restrict__ Ko, float* __restrict__ Vo)
{
    __shared__ union USm {
        struct { float sMi[32][PAD]; float sMjP[8][32][PAD]; } h;
        struct { float As[2][32][68]; float Bs[2][32][68]; } q;
    } sm;

    int x = blockIdx.x;
    if (x < 192) {
        int which = x / 64, tile = x % 64;
        const float* W    = (which == 0) ? Wq : (which == 1) ? Wk : Wv;
        const float* bias = (which == 0) ? bq : (which == 1) ? bk : bv;
        float*       C    = (which == 0) ? Qo : (which == 1) ? Ko : Vo;
        gemm_tile(base, W, bias, C, 512, 512, 512, 512,
                  (tile >> 3) * 64, (tile & 7) * 64, sm.q.As, sm.q.Bs);
        return;
    }

    int idx  = x - 192;
    int z    = idx / 4224;
    int tlin = idx % 4224;
    int t = threadIdx.x;
    int w = t >> 5, lane = t & 31;

    // decode 8-wide triangular tile: F(g) = 260g - 4g^2
    int g = (int)((65.0f - sqrtf(4225.0f - (float)tlin)) * 0.5f);
    g = max(0, min(31, g));
    while (260 * g - 4 * g * g > tlin) g--;
    while (260 * (g + 1) - 4 * (g + 1) * (g + 1) <= tlin) g++;
    int rem = tlin - (260 * g - 4 * g * g);
    int per = 32 - g;
    int i  = 8 * g + rem / per;
    int jt = g + rem % per;
    int j  = jt * 8 + w;

    // Mi -> smem (256 threads, one float4 each)
    {
        const float4* mi4 = (const float4*)(Mg + (size_t)(z * 256 + i) * 1024);
        float4 v = mi4[t];
        *(float4*)&sm.h.sMi[t >> 3][(t & 7) * 4] = v;
    }
    // Mj -> smem (per warp)
    {
        const float4* mj4 = (const float4*)(Mg + (size_t)(z * 256 + j) * 1024);
        for (int fi = lane; fi < 256; fi += 32) {
            float4 v = mj4[fi];
            *(float4*)&sm.h.sMjP[w][fi >> 3][(fi & 7) * 4] = v;
        }
    }
    __syncthreads();

    if (j < i) return;
    if (j == i) {
        if (lane == 0) hol[((size_t)(z * 256 + i)) * 256 + i] = 0.f;
        return;
    }

    int rg = lane >> 2, cg = lane & 3;
    unsigned long long acc[4][4] = {};
    wtile_tn(sm.h.sMi, sm.h.sMjP[w], acc, rg, cg);
    __syncwarp();                            // all lanes done reading Mj
    wtile_store(sm.h.sMjP[w], acc, rg, cg);  // P overwrites Mj
    __syncwarp();

    // t1 = trace(P)
    // t2 = sum_{d,e} acc[d][e-pair] * P[8cg+e][4rg+d]  (own factors from regs;
    // transpose factors via 8 conflict-free LDS.128: banks (8e+4rg)%32, cg
    // drops out of the bank index -> broadcast across cg, full bank coverage)
    float t1 = sm.h.sMjP[w][lane][lane];
    float t2 = 0.f;
#pragma unroll
    for (int e = 0; e < 4; e++) {
        float2 f0 = upk2(acc[0][e]);
        float2 f1 = upk2(acc[1][e]);
        float2 f2 = upk2(acc[2][e]);
        float2 f3 = upk2(acc[3][e]);
        float4 te = *(const float4*)&sm.h.sMjP[w][8 * cg + 2 * e][4 * rg];
        float4 to = *(const float4*)&sm.h.sMjP[w][8 * cg + 2 * e + 1][4 * rg];
        t2 += f0.x * te.x + f1.x * te.y + f2.x * te.z + f3.x * te.w;
        t2 += f0.y * to.x + f1.y * to.y + f2.y * to.z + f3.y * to.w;
    }

#pragma unroll
    for (int off = 16; off; off >>= 1) {
        t1 += __shfl_down_sync(0xffffffffu, t1, off);
        t2 += __shfl_down_sync(0xffffffffu, t2, off);
    }
    if (lane == 0) {
        float h2 = t2 - 2.f * t1 + 32.f;
        float h  = sqrtf(fmaxf(h2, 0.f));
        hol[((size_t)(z * 256 + i)) * 256 + j] = h;
        hol[((size_t)(z * 256 + j)) * 256 + i] = h;
    }
}

// ======================= 4) scores = QK^T/8 - lambda*hol (NT) ===============
__global__ __launch_bounds__(256) void scores_kernel(
    const float* __restrict__ Qm, const float* __restrict__ Km,
    const float* __restrict__ hol, const float* __restrict__ lam,
    float* __restrict__ Sout)
{
    __shared__ float As[2][32][68];
    __shared__ float Bs[2][32][68];
    int zh = blockIdx.z, z = zh >> 3, h = zh & 7;
    int t  = threadIdx.x;
    int tx = t & 15, ty = t >> 4;
    int i0 = blockIdx.y * 64, j0 = blockIdx.x * 64;
    const float* Atile = Qm + (long)z * 131072 + h * 64 + (long)i0 * 512;
    const float* Btile = Km + (long)z * 131072 + h * 64 + (long)j0 * 512;

    int arow = t >> 2, acol = (t & 3) * 8;
    unsigned long long acc2[4][2] = {};

    float4 a0 = *(const float4*)(Atile + (long)arow * 512 + acol);
    float4 a1 = *(const float4*)(Atile + (long)arow * 512 + acol + 4);
    float4 b0 = *(const float4*)(Btile + (long)arow * 512 + acol);
    float4 b1 = *(const float4*)(Btile + (long)arow * 512 + acol + 4);
    As[0][acol+0][arow]=a0.x; As[0][acol+1][arow]=a0.y;
    As[0][acol+2][arow]=a0.z; As[0][acol+3][arow]=a0.w;
    As[0][acol+4][arow]=a1.x; As[0][acol+5][arow]=a1.y;
    As[0][acol+6][arow]=a1.z; As[0][acol+7][arow]=a1.w;
    Bs[0][acol+0][arow]=b0.x; Bs[0][acol+1][arow]=b0.y;
    Bs[0][acol+2][arow]=b0.z; Bs[0][acol+3][arow]=b0.w;
    Bs[0][acol+4][arow]=b1.x; Bs[0][acol+5][arow]=b1.y;
    Bs[0][acol+6][arow]=b1.z; Bs[0][acol+7][arow]=b1.w;
    __syncthreads();
    for (int c = 0; c < 2; c++) {
        int cur = c & 1;
        if (c == 0) {
            a0 = *(const float4*)(Atile + (long)arow * 512 + 32 + acol);
            a1 = *(const float4*)(Atile + (long)arow * 512 + 32 + acol + 4);
            b0 = *(const float4*)(Btile + (long)arow * 512 + 32 + acol);
            b1 = *(const float4*)(Btile + (long)arow * 512 + 32 + acol + 4);
        }
#pragma unroll
        for (int k = 0; k < 32; k++) {
            float4 a4 = *(const float4*)&As[cur][k][ty * 4];
            ulonglong2 bu = *(const ulonglong2*)&Bs[cur][k][tx * 4];
            unsigned long long d0 = pk2(a4.x, a4.x);
            unsigned long long d1 = pk2(a4.y, a4.y);
            unsigned long long d2 = pk2(a4.z, a4.z);
            unsigned long long d3 = pk2(a4.w, a4.w);
            fma2(acc2[0][0], d0, bu.x); fma2(acc2[0][1], d0, bu.y);
            fma2(acc2[1][0], d1, bu.x); fma2(acc2[1][1], d1, bu.y);
            fma2(acc2[2][0], d2, bu.x); fma2(acc2[2][1], d2, bu.y);
            fma2(acc2[3][0], d3, bu.x); fma2(acc2[3][1], d3, bu.y);
        }
        if (c == 0) {
            As[1][acol+0][arow]=a0.x; As[1][acol+1][arow]=a0.y;
            As[1][acol+2][arow]=a0.z; As[1][acol+3][arow]=a0.w;
            As[1][acol+4][arow]=a1.x; As[1][acol+5][arow]=a1.y;
            As[1][acol+6][arow]=a1.z; As[1][acol+7][arow]=a1.w;
            Bs[1][acol+0][arow]=b0.x; Bs[1][acol+1][arow]=b0.y;
            Bs[1][acol+2][arow]=b0.z; Bs[1][acol+3][arow]=b0.w;
            Bs[1][acol+4][arow]=b1.x; Bs[1][acol+5][arow]=b1.y;
            Bs[1][acol+6][arow]=b1.z; Bs[1][acol+7][arow]=b1.w;
        }
        __syncthreads();
    }

    float l = __ldg(lam);
#pragma unroll
    for (int ii = 0; ii < 4; ii++) {
        int irow = i0 + ty * 4 + ii;
        float2 e0 = upk2(acc2[ii][0]);
        float2 e1 = upk2(acc2[ii][1]);
        float vv[4] = {e0.x, e0.y, e1.x, e1.y};
#pragma unroll
        for (int jj = 0; jj < 4; jj++) {
            int jcol = j0 + tx * 4 + jj;
            float v = vv[jj] * 0.125f
                    - l * hol[((size_t)(z * 256 + irow)) * 256 + jcol];
            Sout[(size_t)zh * 65536 + (size_t)irow * 256 + jcol] = v;
        }
    }
}

// ======================= 5) softmax (warp-per-row, shfl-only) ===============
__global__ __launch_bounds__(256) void softmax_kernel(
    float* __restrict__ Sm, const float* __restrict__ hol,
    float* __restrict__ rowpart)
{
    int t = threadIdx.x, w = t >> 5, lane = t & 31;
    int row = blockIdx.x * 8 + w;                 // (z*8+h)*256 + i
    int z = row >> 11;
    int i = row & 255;

    float* rp = Sm + (size_t)row * 256 + lane * 8;
    float4 v0 = *(const float4*)rp;
    float4 v1 = *(const float4*)(rp + 4);

    float m = fmaxf(fmaxf(fmaxf(v0.x, v0.y), fmaxf(v0.z, v0.w)),
                    fmaxf(fmaxf(v1.x, v1.y), fmaxf(v1.z, v1.w)));
#pragma unroll
    for (int o = 16; o; o >>= 1) m = fmaxf(m, __shfl_xor_sync(0xffffffffu, m, o));

    float4 e0, e1;
    e0.x = expf(v0.x - m); e0.y = expf(v0.y - m);
    e0.z = expf(v0.z - m); e0.w = expf(v0.w - m);
    e1.x = expf(v1.x - m); e1.y = expf(v1.y - m);
    e1.z = expf(v1.z - m); e1.w = expf(v1.w - m);

    float s = e0.x + e0.y + e0.z + e0.w + e1.x + e1.y + e1.z + e1.w;
#pragma unroll
    for (int o = 16; o; o >>= 1) s += __shfl_xor_sync(0xffffffffu, s, o);
    float inv = 1.f / s;

    float4 a0, a1;
    a0.x = e0.x * inv; a0.y = e0.y * inv; a0.z = e0.z * inv; a0.w = e0.w * inv;
    a1.x = e1.x * inv; a1.y = e1.y * inv; a1.z = e1.z * inv; a1.w = e1.w * inv;
    *(float4*)rp       = a0;
    *(float4*)(rp + 4) = a1;

    const float* hp = hol + ((size_t)(z * 256 + i)) * 256 + lane * 8;
    float4 h0 = *(const float4*)hp;
    float4 h1 = *(const float4*)(hp + 4);
    float d = a0.x*h0.x + a0.y*h0.y + a0.z*h0.z + a0.w*h0.w
            + a1.x*h1.x + a1.y*h1.y + a1.z*h1.z + a1.w*h1.w;
#pragma unroll
    for (int o = 16; o; o >>= 1) d += __shfl_xor_sync(0xffffffffu, d, o);
    if (lane == 0) rowpart[row] = d;
}

// =============== 6+8) tail1: attn@V (64 blocks) || head-avg (512) ===========
__global__ __launch_bounds__(256) void tail1_kernel(
    const float* __restrict__ attn, const float* __restrict__ V,
    float* __restrict__ outpre, float* __restrict__ avg)
{
    __shared__ float As[2][32][68];
    __shared__ float Bs[2][32][68];
    int x = blockIdx.x;
    if (x < 64) {
        int bz = x >> 2, by = x & 3;
        const float* A = attn + (long)bz * 65536;
        const float* B = V + (long)(bz >> 3) * 131072 + (long)(bz & 7) * 64;
        float* C = outpre + (long)(bz >> 3) * 131072 + (long)(bz & 7) * 64;
        gemm_tile(A, B, nullptr, C, 256, 256, 512, 512, by * 64, 0, As, Bs);
    } else {
        size_t idx = (size_t)(x - 64) * 256 + threadIdx.x;
        size_t z  = idx >> 16;
        size_t ij = idx & 65535;
        float s = 0.f;
#pragma unroll
        for (int h = 0; h < 8; h++) s += attn[(z * 8 + h) * 65536 + ij];
        avg[idx] = s * 0.125f;
    }
}

// ===== 7+9+11) tail2: @Wo+bo (64) || avg@fiber (128) || total_hol (1) =======
__global__ __launch_bounds__(256) void tail2_kernel(
    const float* __restrict__ outpre, const float* __restrict__ Wo,
    const float* __restrict__ bo, float* __restrict__ outp,
    const float* __restrict__ avg, const float* __restrict__ fiber,
    float* __restrict__ fpre,
    const float* __restrict__ rowpart, float* __restrict__ totv)
{
    __shared__ float As[2][32][68];
    __shared__ float Bs[2][32][68];
    int x = blockIdx.x;
    if (x < 64) {
        int by = x >> 3, bx = x & 7;
        gemm_tile(outpre, Wo, bo, outp, 512, 512, 512, 512,
                  by * 64, bx * 64, As, Bs);
    } else if (x < 192) {
        int v = x - 64;
        int bz = v >> 6, r = v & 63;
        int by = r >> 4, bx = r & 15;
        gemm_tile(avg + (long)bz * 65536, fiber + (long)bz * 262144, nullptr,
                  fpre + (long)bz * 262144, 256, 256, 1024, 1024,
                  by * 64, bx * 64, As, Bs);
    } else {
        // total_hol reduction over rowpart[4096]
        int t = threadIdx.x, lane = t & 31, w = t >> 5;
        float s = 0.f;
#pragma unroll
        for (int q = 0; q < 16; q++) s += rowpart[t + 256 * q];
#pragma unroll
        for (int o = 16; o; o >>= 1) s += __shfl_xor_sync(0xffffffffu, s, o);
        float* red = &As[0][0][0];
        if (lane == 0) red[w] = s;
        __syncthreads();
        if (t == 0) {
            float tot = 0.f;
#pragma unroll
            for (int q = 0; q < 8; q++) tot += red[q];
            *totv = tot;
        }
    }
}

// ======= 10) Newton-Schulz polar (warp-per-matrix, R6 exact) ================
__global__ __launch_bounds__(128) void ns_kernel(
    const float* __restrict__ Fin, float* __restrict__ Fout)
{
    __shared__ float X[4][32][PAD], S[4][32][PAD];
    int t = threadIdx.x;
    int w = t >> 5, lane = t & 31;
    int rg = lane >> 2, cg = lane & 3;
    int zi = blockIdx.x * 4 + w;

    const float4* f4 = (const float4*)(Fin + (size_t)zi * 1024);
    float4 vals[8];
    float sq = 0.f;
#pragma unroll
    for (int q = 0; q < 8; q++) {
        float4 v = f4[q * 32 + lane];
        vals[q] = v;
        sq += v.x*v.x + v.y*v.y + v.z*v.z + v.w*v.w;
    }
#pragma unroll
    for (int o = 16; o; o >>= 1) sq += __shfl_xor_sync(0xffffffffu, sq, o);
    float scale = rsqrtf(fmaxf(sq, 1e-30f));
#pragma unroll
    for (int q = 0; q < 8; q++) {
        int fi = q * 32 + lane;
        float4 v = vals[q];
        v.x *= scale; v.y *= scale; v.z *= scale; v.w *= scale;
        *(float4*)&X[w][fi >> 3][(fi & 7) * 4] = v;
    }
    __syncwarp();

    for (int iter = 0; iter < 64; iter++) {
        unsigned long long acc[4][4] = {};
        wtile_tn(X[w], X[w], acc, rg, cg);

        bool bad = false;
#pragma unroll
        for (int d = 0; d < 4; d++) {
            int a = 4 * rg + d;
#pragma unroll
            for (int e = 0; e < 4; e++) {
                float2 f = upk2(acc[d][e]);
                int b0i = 8 * cg + 2 * e, b1i = b0i + 1;
                bad |= fabsf(f.x - ((a == b0i) ? 1.f : 0.f)) > 2e-5f;
                bad |= fabsf(f.y - ((a == b1i) ? 1.f : 0.f)) > 2e-5f;
            }
        }
        if (!__any_sync(0xffffffffu, bad)) break;

        wtile_store(S[w], acc, rg, cg);
        __syncwarp();

        unsigned long long acc2[4][4] = {};
        wtile_nn(X[w], S[w], acc2, rg, cg);
        float y[4][8];
#pragma unroll
        for (int d = 0; d < 4; d++) {
            int row = 4 * rg + d;
            float4 x0 = *(const float4*)&X[w][row][8 * cg];
            float4 x1 = *(const float4*)&X[w][row][8 * cg + 4];
            float2 p0 = upk2(acc2[d][0]);
            float2 p1 = upk2(acc2[d][1]);
            float2 p2 = upk2(acc2[d][2]);
            float2 p3 = upk2(acc2[d][3]);
            y[d][0] = 1.5f*x0.x - 0.5f*p0.x; y[d][1] = 1.5f*x0.y - 0.5f*p0.y;
            y[d][2] = 1.5f*x0.z - 0.5f*p1.x; y[d][3] = 1.5f*x0.w - 0.5f*p1.y;
            y[d][4] = 1.5f*x1.x - 0.5f*p2.x; y[d][5] = 1.5f*x1.y - 0.5f*p2.y;
            y[d][6] = 1.5f*x1.z - 0.5f*p3.x; y[d][7] = 1.5f*x1.w - 0.5f*p3.y;
        }
        __syncwarp();
#pragma unroll
        for (int d = 0; d < 4; d++) {
            int row = 4 * rg + d;
            *(float4*)&X[w][row][8 * cg]     = make_float4(y[d][0], y[d][1], y[d][2], y[d][3]);
            *(float4*)&X[w][row][8 * cg + 4] = make_float4(y[d][4], y[d][5], y[d][6], y[d][7]);
        }
        __syncwarp();
    }

    float* fo = Fout + (size_t)zi * 1024;
#pragma unroll
    for (int q = 0; q < 8; q++) {
        int fi = q * 32 + lane;
        float4 v = *(const float4*)&X[w][fi >> 3][(fi & 7) * 4];
        *(float4*)(fo + fi * 4) = v;
    }
}

// ======================= launcher ===========================================
extern "C" void kernel_launch(void* const* d_in, const int* in_sizes, int n_in,
                              void* d_out, int out_size)
{
    const float* base  = (const float*)d_in[0];
    const float* fiber = (const float*)d_in[1];
    const float* conn  = (const float*)d_in[2];
    const float* gen   = (const float*)d_in[3];
    const float* Wq    = (const float*)d_in[4];
    const float* bq    = (const float*)d_in[5];
    const float* Wk    = (const float*)d_in[6];
    const float* bk    = (const float*)d_in[7];
    const float* Wv    = (const float*)d_in[8];
    const float* bv    = (const float*)d_in[9];
    const float* Wo    = (const float*)d_in[10];
    const float* bo    = (const float*)d_in[11];
    const float* lam   = (const float*)d_in[12];
    float* out = (float*)d_out;

    float* sc;
    cudaGetSymbolAddress((void**)&sc, g_scratch);
    float* M       = sc;
    float* hol     = M + 524288;
    float* Q       = hol + 131072;
    float* Km      = Q + 262144;
    float* V       = Km + 262144;
    float* attn    = V + 262144;
    float* avg     = attn + 1048576;
    float* outpre  = avg + 131072;
    float* fpre    = outpre + 262144;
    float* rowpart = fpre + 524288;

    // 1) expm + M
    expm_kernel<<<256, 64>>>(conn, gen, M);

    // 2+3) QKV (192 blocks) fused with holonomy
    hol_qkv_kernel<<<192 + 8448, 256>>>(M, hol, base, Wq, Wk, Wv,
                                        bq, bk, bv, Q, Km, V);

    // 4) scores
    scores_kernel<<<dim3(4, 4, 16), 256>>>(Q, Km, hol, lam, attn);

    // 5) softmax (warp per row)
    softmax_kernel<<<512, 256>>>(attn, hol, rowpart);

    // 6+8) attn@V || head-average
    tail1_kernel<<<576, 256>>>(attn, V, outpre, avg);

    // 7+9+11) @Wo+bo || avg@fiber || total_hol
    tail2_kernel<<<193, 256>>>(outpre, Wo, bo, out, avg, fiber, fpre,
                               rowpart, out + 786432);

    // 10) polar projection (warp-autonomous NS)
    ns_kernel<<<128, 128>>>(fpre, out + 262144);
}

// round 16
// speedup vs baseline: 1.0555x; 1.0555x over previous
#include <cuda_runtime.h>
#include <cuda_bf16.h>

// ---------------------------------------------------------------------------
// ParallelTransportAttention  (B=2, S=256, D=512, H=8, Dh=64, df=32, rank=8)
// Round 16: exact revert to R14 champion (297.3us).
//   R15's acc-register epilogue spilled under the 64-reg cap (regression);
//   R14's smem epilogue keeps acc liveness minimal. All components as R14.
// ---------------------------------------------------------------------------

__device__ __align__(256) float g_scratch[3411968];

#define PAD 36

// ---------------- packed f32x2 helpers --------------------------------------
__device__ __forceinline__ unsigned long long pk2(float x, float y) {
    unsigned long long r;
    asm("mov.b64 %0, {%1,%2};" : "=l"(r) : "f"(x), "f"(y));
    return r;
}
__device__ __forceinline__ void fma2(unsigned long long& d,
                                     unsigned long long a, unsigned long long b) {
    asm("fma.rn.f32x2 %0, %1, %2, %0;" : "+l"(d) : "l"(a), "l"(b));
}
__device__ __forceinline__ float2 upk2(unsigned long long v) {
    float2 f;
    asm("mov.b64 {%0,%1}, %2;" : "=f"(f.x), "=f"(f.y) : "l"(v));
    return f;
}

// ---------------- warp-tiled 32x32x32 matmuls -------------------------------
__device__ __forceinline__ void wtile_tn(const float (*A)[PAD], const float (*B)[PAD],
                                         unsigned long long acc[4][4], int rg, int cg) {
#pragma unroll
    for (int k = 0; k < 32; k++) {
        float4 av = *(const float4*)&A[k][4 * rg];
        ulonglong2 b01 = *(const ulonglong2*)&B[k][8 * cg];
        ulonglong2 b23 = *(const ulonglong2*)&B[k][8 * cg + 4];
        unsigned long long a0 = pk2(av.x, av.x);
        unsigned long long a1 = pk2(av.y, av.y);
        unsigned long long a2 = pk2(av.z, av.z);
        unsigned long long a3 = pk2(av.w, av.w);
        fma2(acc[0][0], a0, b01.x); fma2(acc[0][1], a0, b01.y);
        fma2(acc[0][2], a0, b23.x); fma2(acc[0][3], a0, b23.y);
        fma2(acc[1][0], a1, b01.x); fma2(acc[1][1], a1, b01.y);
        fma2(acc[1][2], a1, b23.x); fma2(acc[1][3], a1, b23.y);
        fma2(acc[2][0], a2, b01.x); fma2(acc[2][1], a2, b01.y);
        fma2(acc[2][2], a2, b23.x); fma2(acc[2][3], a2, b23.y);
        fma2(acc[3][0], a3, b01.x); fma2(acc[3][1], a3, b01.y);
        fma2(acc[3][2], a3, b23.x); fma2(acc[3][3], a3, b23.y);
    }
}

__device__ __forceinline__ void wtile_nn(const float (*A)[PAD], const float (*B)[PAD],
                                         unsigned long long acc[4][4], int rg, int cg) {
#pragma unroll
    for (int k0 = 0; k0 < 32; k0 += 4) {
        float4 ar0 = *(const float4*)&A[4 * rg + 0][k0];
        float4 ar1 = *(const float4*)&A[4 * rg + 1][k0];
        float4 ar2 = *(const float4*)&A[4 * rg + 2][k0];
        float4 ar3 = *(const float4*)&A[4 * rg + 3][k0];
        const float* a0f = (const float*)&ar0;
        const float* a1f = (const float*)&ar1;
        const float* a2f = (const float*)&ar2;
        const float* a3f = (const float*)&ar3;
#pragma unroll
        for (int kk = 0; kk < 4; kk++) {
            ulonglong2 b01 = *(const ulonglong2*)&B[k0 + kk][8 * cg];
            ulonglong2 b23 = *(const ulonglong2*)&B[k0 + kk][8 * cg + 4];
            unsigned long long a0 = pk2(a0f[kk], a0f[kk]);
            unsigned long long a1 = pk2(a1f[kk], a1f[kk]);
            unsigned long long a2 = pk2(a2f[kk], a2f[kk]);
            unsigned long long a3 = pk2(a3f[kk], a3f[kk]);
            fma2(acc[0][0], a0, b01.x); fma2(acc[0][1], a0, b01.y);
            fma2(acc[0][2], a0, b23.x); fma2(acc[0][3], a0, b23.y);
            fma2(acc[1][0], a1, b01.x); fma2(acc[1][1], a1, b01.y);
            fma2(acc[1][2], a1, b23.x); fma2(acc[1][3], a1, b23.y);
            fma2(acc[2][0], a2, b01.x); fma2(acc[2][1], a2, b01.y);
            fma2(acc[2][2], a2, b23.x); fma2(acc[2][3], a2, b23.y);
            fma2(acc[3][0], a3, b01.x); fma2(acc[3][1], a3, b01.y);
            fma2(acc[3][2], a3, b23.x); fma2(acc[3][3], a3, b23.y);
        }
    }
}

__device__ __forceinline__ void wtile_store(float (*C)[PAD],
                                            const unsigned long long acc[4][4],
                                            int rg, int cg) {
#pragma unroll
    for (int d = 0; d < 4; d++) {
        ulonglong2 v0; v0.x = acc[d][0]; v0.y = acc[d][1];
        ulonglong2 v1; v1.x = acc[d][2]; v1.y = acc[d][3];
        *(ulonglong2*)&C[4 * rg + d][8 * cg]     = v0;
        *(ulonglong2*)&C[4 * rg + d][8 * cg + 4] = v1;
    }
}

// ================= double-buffered 64x64 GEMM tile (device fn) ==============
__device__ __forceinline__ void gemm_tile(
    const float* __restrict__ A, const float* __restrict__ B,
    const float* __restrict__ bias, float* __restrict__ C,
    int K, int lda, int ldb, int ldc, int row0, int col0,
    float (*As)[32][68], float (*Bs)[32][68])
{
    int t  = threadIdx.x;
    int tx = t & 15, ty = t >> 4;
    const float* Atile = A + (long)row0 * lda;
    const float* Btile = B + col0;
    int NC = K >> 5;

    unsigned long long acc2[4][2] = {};
    int arow = t >> 2, acol = (t & 3) * 8;
    int brow = t >> 3, bcol = (t & 7) * 8;

    float4 a0 = *(const float4*)(Atile + (long)arow * lda + acol);
    float4 a1 = *(const float4*)(Atile + (long)arow * lda + acol + 4);
    float4 b0 = *(const float4*)(Btile + (long)brow * ldb + bcol);
    float4 b1 = *(const float4*)(Btile + (long)brow * ldb + bcol + 4);
    As[0][acol+0][arow]=a0.x; As[0][acol+1][arow]=a0.y;
    As[0][acol+2][arow]=a0.z; As[0][acol+3][arow]=a0.w;
    As[0][acol+4][arow]=a1.x; As[0][acol+5][arow]=a1.y;
    As[0][acol+6][arow]=a1.z; As[0][acol+7][arow]=a1.w;
    *(float4*)&Bs[0][brow][bcol]   = b0;
    *(float4*)&Bs[0][brow][bcol+4] = b1;
    __syncthreads();
    for (int c = 0; c < NC; c++) {
        int cur = c & 1;
        if (c + 1 < NC) {
            const float* Ap = Atile + (c + 1) * 32;
            const float* Bp = Btile + (long)(c + 1) * 32 * ldb;
            a0 = *(const float4*)(Ap + (long)arow * lda + acol);
            a1 = *(const float4*)(Ap + (long)arow * lda + acol + 4);
            b0 = *(const float4*)(Bp + (long)brow * ldb + bcol);
            b1 = *(const float4*)(Bp + (long)brow * ldb + bcol + 4);
        }
#pragma unroll
        for (int k = 0; k < 32; k++) {
            float4 a4 = *(const float4*)&As[cur][k][ty * 4];
            ulonglong2 bu = *(const ulonglong2*)&Bs[cur][k][tx * 4];
            unsigned long long d0 = pk2(a4.x, a4.x);
            unsigned long long d1 = pk2(a4.y, a4.y);
            unsigned long long d2 = pk2(a4.z, a4.z);
            unsigned long long d3 = pk2(a4.w, a4.w);
            fma2(acc2[0][0], d0, bu.x); fma2(acc2[0][1], d0, bu.y);
            fma2(acc2[1][0], d1, bu.x); fma2(acc2[1][1], d1, bu.y);
            fma2(acc2[2][0], d2, bu.x); fma2(acc2[2][1], d2, bu.y);
            fma2(acc2[3][0], d3, bu.x); fma2(acc2[3][1], d3, bu.y);
        }
        if (c + 1 < NC) {
            int nxt = cur ^ 1;
            As[nxt][acol+0][arow]=a0.x; As[nxt][acol+1][arow]=a0.y;
            As[nxt][acol+2][arow]=a0.z; As[nxt][acol+3][arow]=a0.w;
            As[nxt][acol+4][arow]=a1.x; As[nxt][acol+5][arow]=a1.y;
            As[nxt][acol+6][arow]=a1.z; As[nxt][acol+7][arow]=a1.w;
            *(float4*)&Bs[nxt][brow][bcol]   = b0;
            *(float4*)&Bs[nxt][brow][bcol+4] = b1;
        }
        __syncthreads();
    }

    float bv4[4] = {0.f, 0.f, 0.f, 0.f};
    if (bias) {
#pragma unroll
        for (int j = 0; j < 4; j++) bv4[j] = bias[col0 + tx * 4 + j];
    }
#pragma unroll
    for (int ii = 0; ii < 4; ii++) {
        float2 e0 = upk2(acc2[ii][0]);
        float2 e1 = upk2(acc2[ii][1]);
        float4 o;
        o.x = e0.x + bv4[0]; o.y = e0.y + bv4[1];
        o.z = e1.x + bv4[2]; o.w = e1.y + bv4[3];
        *(float4*)(C + (long)(row0 + ty * 4 + ii) * ldc + col0 + tx * 4) = o;
    }
}

// ======================= 1) expm + M (warp-per-matrix) ======================
__global__ __launch_bounds__(64) void expm_kernel(
    const float* __restrict__ conn, const float* __restrict__ gen,
    float* __restrict__ Mout)
{
    __shared__ float sA[2][32][PAD], sP[2][32][PAD], sT[2][32][PAD];
    int t = threadIdx.x;
    int w = t >> 5, lane = t & 31;
    int rg = lane >> 2, cg = lane & 3;
    int zs = blockIdx.x * 2 + w;

    float c8[8];
#pragma unroll
    for (int r = 0; r < 8; r++) c8[r] = conn[zs * 8 + r];

    float atile[4][8];
#pragma unroll
    for (int d = 0; d < 4; d++) {
        int row = 4 * rg + d;
#pragma unroll
        for (int h = 0; h < 2; h++) {
            float4 v = make_float4(0.f, 0.f, 0.f, 0.f);
#pragma unroll
            for (int r = 0; r < 8; r++) {
                float4 g = *(const float4*)(gen + r * 1024 + row * 32 + 8 * cg + 4 * h);
                v.x += c8[r] * g.x; v.y += c8[r] * g.y;
                v.z += c8[r] * g.z; v.w += c8[r] * g.w;
            }
            atile[d][4*h+0] = v.x * 0.1f; atile[d][4*h+1] = v.y * 0.1f;
            atile[d][4*h+2] = v.z * 0.1f; atile[d][4*h+3] = v.w * 0.1f;
        }
#pragma unroll
        for (int e = 0; e < 8; e++) sA[w][row][8 * cg + e] = atile[d][e];
    }
    __syncwarp();

    float cs = 0.f;
#pragma unroll
    for (int a = 0; a < 32; a++) cs += fabsf(sA[w][a][lane]);
    float nrm = cs;
#pragma unroll
    for (int o = 16; o; o >>= 1) nrm = fmaxf(nrm, __shfl_xor_sync(0xffffffffu, nrm, o));
    int s = 0;
    while (nrm > 0.25f * ldexpf(1.f, s) && s < 12) s++;
    float sc = ldexpf(1.f, -s);

    float treg[4][8];
#pragma unroll
    for (int d = 0; d < 4; d++) {
        int row = 4 * rg + d;
#pragma unroll
        for (int e = 0; e < 8; e++) {
            float a = atile[d][e] * sc;
            sA[w][row][8 * cg + e] = a;
            sP[w][row][8 * cg + e] = a;
            treg[d][e] = a + ((row == 8 * cg + e) ? 1.f : 0.f);
        }
    }
    __syncwarp();

    for (int k = 2; k <= 9; k++) {
        unsigned long long acc[4][4] = {};
        wtile_nn(sP[w], sA[w], acc, rg, cg);
        float inv = 1.f / (float)k;
        __syncwarp();
#pragma unroll
        for (int d = 0; d < 4; d++) {
#pragma unroll
            for (int e = 0; e < 4; e++) {
                float2 f = upk2(acc[d][e]);
                float t0 = f.x * inv, t1 = f.y * inv;
                sP[w][4 * rg + d][8 * cg + 2 * e]     = t0;
                sP[w][4 * rg + d][8 * cg + 2 * e + 1] = t1;
                treg[d][2 * e]     += t0;
                treg[d][2 * e + 1] += t1;
            }
        }
        __syncwarp();
    }
#pragma unroll
    for (int d = 0; d < 4; d++)
#pragma unroll
        for (int e = 0; e < 8; e++)
            sT[w][4 * rg + d][8 * cg + e] = treg[d][e];
    __syncwarp();

    for (int it = 0; it < s; it++) {
        unsigned long long acc[4][4] = {};
        wtile_nn(sT[w], sT[w], acc, rg, cg);
        __syncwarp();
        wtile_store(sT[w], acc, rg, cg);
        __syncwarp();
    }

    unsigned long long acc[4][4] = {};
    wtile_tn(sT[w], sT[w], acc, rg, cg);
    float* mo = Mout + (size_t)zs * 1024;
#pragma unroll
    for (int d = 0; d < 4; d++) {
        float2 f0 = upk2(acc[d][0]);
        float2 f1 = upk2(acc[d][1]);
        float2 f2 = upk2(acc[d][2]);
        float2 f3 = upk2(acc[d][3]);
        float4 o0 = make_float4(f0.x, f0.y, f1.x, f1.y);
        float4 o1 = make_float4(f2.x, f2.y, f3.x, f3.y);
        *(float4*)(mo + (4 * rg + d) * 32 + 8 * cg)     = o0;
        *(float4*)(mo + (4 * rg + d) * 32 + 8 * cg + 4) = o1;
    }
}

// ============= 2+3) fused: QKV GEMMs (blocks 0..191) + holonomy =============
// hol: block = (z, i, 8-wide j tile); warp w -> j = jt*8+w; P stored over Mj.
// __launch_bounds__(256, 4): 64-reg cap -> 4 CTAs/SM (validated R14 win).
__global__ __launch_bounds__(256, 4) void hol_qkv_kernel(
    const float* __restrict__ Mg, float* __restrict__ hol,
    const float* __restrict__ base,
    const float* __restrict__ Wq, const float* __restrict__ Wk, const float* __restrict__ Wv,
    const float* __restrict__ bq, const float* __restrict__ bk, const float* __restrict__ bv,
    float* __restrict__ Qo, float* __restrict__ Ko, float* __restrict__ Vo)
{
    __shared__ union USm {
        struct { float sMi[32][PAD]; float sMjP[8][32][PAD]; } h;
        struct { float As[2][32][68]; float Bs[2][32][68]; } q;
    } sm;

    int x = blockIdx.x;
    if (x < 192) {
        int which = x / 64, tile = x % 64;
        const float* W    = (which == 0) ? Wq : (which == 1) ? Wk : Wv;
        const float* bias = (which == 0) ? bq : (which == 1) ? bk : bv;
        float*       C    = (which == 0) ? Qo : (which == 1) ? Ko : Vo;
        gemm_tile(base, W, bias, C, 512, 512, 512, 512,
                  (tile >> 3) * 64, (tile & 7) * 64, sm.q.As, sm.q.Bs);
        return;
    }

    int idx  = x - 192;
    int z    = idx / 4224;
    int tlin = idx % 4224;
    int t = threadIdx.x;
    int w = t >> 5, lane = t & 31;

    // decode 8-wide triangular tile: F(g) = 260g - 4g^2
    int g = (int)((65.0f - sqrtf(4225.0f - (float)tlin)) * 0.5f);
    g = max(0, min(31, g));
    while (260 * g - 4 * g * g > tlin) g--;
    while (260 * (g + 1) - 4 * (g + 1) * (g + 1) <= tlin) g++;
    int rem = tlin - (260 * g - 4 * g * g);
    int per = 32 - g;
    int i  = 8 * g + rem / per;
    int jt = g + rem % per;
    int j  = jt * 8 + w;

    // Mi -> smem (256 threads, one float4 each)
    {
        const float4* mi4 = (const float4*)(Mg + (size_t)(z * 256 + i) * 1024);
        float4 v = mi4[t];
        *(float4*)&sm.h.sMi[t >> 3][(t & 7) * 4] = v;
    }
    // Mj -> smem (per warp)
    {
        const float4* mj4 = (const float4*)(Mg + (size_t)(z * 256 + j) * 1024);
        for (int fi = lane; fi < 256; fi += 32) {
            float4 v = mj4[fi];
            *(float4*)&sm.h.sMjP[w][fi >> 3][(fi & 7) * 4] = v;
        }
    }
    __syncthreads();

    if (j < i) return;
    if (j == i) {
        if (lane == 0) hol[((size_t)(z * 256 + i)) * 256 + i] = 0.f;
        return;
    }

    int rg = lane >> 2, cg = lane & 3;
    unsigned long long acc[4][4] = {};
    wtile_tn(sm.h.sMi, sm.h.sMjP[w], acc, rg, cg);
    __syncwarp();                            // all lanes done reading Mj
    wtile_store(sm.h.sMjP[w], acc, rg, cg);  // P overwrites Mj
    __syncwarp();

    // t1 = trace(P); t2 = sum_a P[lane][a]*P[a][lane] (vectorized row reads)
    float t1 = sm.h.sMjP[w][lane][lane];
    float t2 = 0.f;
#pragma unroll
    for (int q = 0; q < 8; q++) {
        float4 rv = *(const float4*)&sm.h.sMjP[w][lane][4 * q];
        t2 += rv.x * sm.h.sMjP[w][4 * q + 0][lane];
        t2 += rv.y * sm.h.sMjP[w][4 * q + 1][lane];
        t2 += rv.z * sm.h.sMjP[w][4 * q + 2][lane];
        t2 += rv.w * sm.h.sMjP[w][4 * q + 3][lane];
    }

#pragma unroll
    for (int off = 16; off; off >>= 1) {
        t1 += __shfl_down_sync(0xffffffffu, t1, off);
        t2 += __shfl_down_sync(0xffffffffu, t2, off);
    }
    if (lane == 0) {
        float h2 = t2 - 2.f * t1 + 32.f;
        float h  = sqrtf(fmaxf(h2, 0.f));
        hol[((size_t)(z * 256 + i)) * 256 + j] = h;
        hol[((size_t)(z * 256 + j)) * 256 + i] = h;
    }
}

// ======================= 4) scores = QK^T/8 - lambda*hol (NT) ===============
__global__ __launch_bounds__(256) void scores_kernel(
    const float* __restrict__ Qm, const float* __restrict__ Km,
    const float* __restrict__ hol, const float* __restrict__ lam,
    float* __restrict__ Sout)
{
    __shared__ float As[2][32][68];
    __shared__ float Bs[2][32][68];
    int zh = blockIdx.z, z = zh >> 3, h = zh & 7;
    int t  = threadIdx.x;
    int tx = t & 15, ty = t >> 4;
    int i0 = blockIdx.y * 64, j0 = blockIdx.x * 64;
    const float* Atile = Qm + (long)z * 131072 + h * 64 + (long)i0 * 512;
    const float* Btile = Km + (long)z * 131072 + h * 64 + (long)j0 * 512;

    int arow = t >> 2, acol = (t & 3) * 8;
    unsigned long long acc2[4][2] = {};

    float4 a0 = *(const float4*)(Atile + (long)arow * 512 + acol);
    float4 a1 = *(const float4*)(Atile + (long)arow * 512 + acol + 4);
    float4 b0 = *(const float4*)(Btile + (long)arow * 512 + acol);
    float4 b1 = *(const float4*)(Btile + (long)arow * 512 + acol + 4);
    As[0][acol+0][arow]=a0.x; As[0][acol+1][arow]=a0.y;
    As[0][acol+2][arow]=a0.z; As[0][acol+3][arow]=a0.w;
    As[0][acol+4][arow]=a1.x; As[0][acol+5][arow]=a1.y;
    As[0][acol+6][arow]=a1.z; As[0][acol+7][arow]=a1.w;
    Bs[0][acol+0][arow]=b0.x; Bs[0][acol+1][arow]=b0.y;
    Bs[0][acol+2][arow]=b0.z; Bs[0][acol+3][arow]=b0.w;
    Bs[0][acol+4][arow]=b1.x; Bs[0][acol+5][arow]=b1.y;
    Bs[0][acol+6][arow]=b1.z; Bs[0][acol+7][arow]=b1.w;
    __syncthreads();
    for (int c = 0; c < 2; c++) {
        int cur = c & 1;
        if (c == 0) {
            a0 = *(const float4*)(Atile + (long)arow * 512 + 32 + acol);
            a1 = *(const float4*)(Atile + (long)arow * 512 + 32 + acol + 4);
            b0 = *(const float4*)(Btile + (long)arow * 512 + 32 + acol);
            b1 = *(const float4*)(Btile + (long)arow * 512 + 32 + acol + 4);
        }
#pragma unroll
        for (int k = 0; k < 32; k++) {
            float4 a4 = *(const float4*)&As[cur][k][ty * 4];
            ulonglong2 bu = *(const ulonglong2*)&Bs[cur][k][tx * 4];
            unsigned long long d0 = pk2(a4.x, a4.x);
            unsigned long long d1 = pk2(a4.y, a4.y);
            unsigned long long d2 = pk2(a4.z, a4.z);
            unsigned long long d3 = pk2(a4.w, a4.w);
            fma2(acc2[0][0], d0, bu.x); fma2(acc2[0][1], d0, bu.y);
            fma2(acc2[1][0], d1, bu.x); fma2(acc2[1][1], d1, bu.y);
            fma2(acc2[2][0], d2, bu.x); fma2(acc2[2][1], d2, bu.y);
            fma2(acc2[3][0], d3, bu.x); fma2(acc2[3][1], d3, bu.y);
        }
        if (c == 0) {
            As[1][acol+0][arow]=a0.x; As[1][acol+1][arow]=a0.y;
            As[1][acol+2][arow]=a0.z; As[1][acol+3][arow]=a0.w;
            As[1][acol+4][arow]=a1.x; As[1][acol+5][arow]=a1.y;
            As[1][acol+6][arow]=a1.z; As[1][acol+7][arow]=a1.w;
            Bs[1][acol+0][arow]=b0.x; Bs[1][acol+1][arow]=b0.y;
            Bs[1][acol+2][arow]=b0.z; Bs[1][acol+3][arow]=b0.w;
            Bs[1][acol+4][arow]=b1.x; Bs[1][acol+5][arow]=b1.y;
            Bs[1][acol+6][arow]=b1.z; Bs[1][acol+7][arow]=b1.w;
        }
        __syncthreads();
    }

    float l = __ldg(lam);
#pragma unroll
    for (int ii = 0; ii < 4; ii++) {
        int irow = i0 + ty * 4 + ii;
        float2 e0 = upk2(acc2[ii][0]);
        float2 e1 = upk2(acc2[ii][1]);
        float vv[4] = {e0.x, e0.y, e1.x, e1.y};
#pragma unroll
        for (int jj = 0; jj < 4; jj++) {
            int jcol = j0 + tx * 4 + jj;
            float v = vv[jj] * 0.125f
                    - l * hol[((size_t)(z * 256 + irow)) * 256 + jcol];
            Sout[(size_t)zh * 65536 + (size_t)irow * 256 + jcol] = v;
        }
    }
}

// ======================= 5) softmax (warp-per-row, shfl-only) ===============
__global__ __launch_bounds__(256) void softmax_kernel(
    float* __restrict__ Sm, const float* __restrict__ hol,
    float* __restrict__ rowpart)
{
    int t = threadIdx.x, w = t >> 5, lane = t & 31;
    int row = blockIdx.x * 8 + w;                 // (z*8+h)*256 + i
    int z = row >> 11;
    int i = row & 255;

    float* rp = Sm + (size_t)row * 256 + lane * 8;
    float4 v0 = *(const float4*)rp;
    float4 v1 = *(const float4*)(rp + 4);

    float m = fmaxf(fmaxf(fmaxf(v0.x, v0.y), fmaxf(v0.z, v0.w)),
                    fmaxf(fmaxf(v1.x, v1.y), fmaxf(v1.z, v1.w)));
#pragma unroll
    for (int o = 16; o; o >>= 1) m = fmaxf(m, __shfl_xor_sync(0xffffffffu, m, o));

    float4 e0, e1;
    e0.x = expf(v0.x - m); e0.y = expf(v0.y - m);
    e0.z = expf(v0.z - m); e0.w = expf(v0.w - m);
    e1.x = expf(v1.x - m); e1.y = expf(v1.y - m);
    e1.z = expf(v1.z - m); e1.w = expf(v1.w - m);

    float s = e0.x + e0.y + e0.z + e0.w + e1.x + e1.y + e1.z + e1.w;
#pragma unroll
    for (int o = 16; o; o >>= 1) s += __shfl_xor_sync(0xffffffffu, s, o);
    float inv = 1.f / s;

    float4 a0, a1;
    a0.x = e0.x * inv; a0.y = e0.y * inv; a0.z = e0.z * inv; a0.w = e0.w * inv;
    a1.x = e1.x * inv; a1.y = e1.y * inv; a1.z = e1.z * inv; a1.w = e1.w * inv;
    *(float4*)rp       = a0;
    *(float4*)(rp + 4) = a1;

    const float* hp = hol + ((size_t)(z * 256 + i)) * 256 + lane * 8;
    float4 h0 = *(const float4*)hp;
    float4 h1 = *(const float4*)(hp + 4);
    float d = a0.x*h0.x + a0.y*h0.y + a0.z*h0.z + a0.w*h0.w
            + a1.x*h1.x + a1.y*h1.y + a1.z*h1.z + a1.w*h1.w;
#pragma unroll
    for (int o = 16; o; o >>= 1) d += __shfl_xor_sync(0xffffffffu, d, o);
    if (lane == 0) rowpart[row] = d;
}

// =============== 6+8) tail1: attn@V (64 blocks) || head-avg (512) ===========
__global__ __launch_bounds__(256) void tail1_kernel(
    const float* __restrict__ attn, const float* __restrict__ V,
    float* __restrict__ outpre, float* __restrict__ avg)
{
    __shared__ float As[2][32][68];
    __shared__ float Bs[2][32][68];
    int x = blockIdx.x;
    if (x < 64) {
        int bz = x >> 2, by = x & 3;
        const float* A = attn + (long)bz * 65536;
        const float* B = V + (long)(bz >> 3) * 131072 + (long)(bz & 7) * 64;
        float* C = outpre + (long)(bz >> 3) * 131072 + (long)(bz & 7) * 64;
        gemm_tile(A, B, nullptr, C, 256, 256, 512, 512, by * 64, 0, As, Bs);
    } else {
        size_t idx = (size_t)(x - 64) * 256 + threadIdx.x;
        size_t z  = idx >> 16;
        size_t ij = idx & 65535;
        float s = 0.f;
#pragma unroll
        for (int h = 0; h < 8; h++) s += attn[(z * 8 + h) * 65536 + ij];
        avg[idx] = s * 0.125f;
    }
}

// ===== 7+9+11) tail2: @Wo+bo (64) || avg@fiber (128) || total_hol (1) =======
__global__ __launch_bounds__(256) void tail2_kernel(
    const float* __restrict__ outpre, const float* __restrict__ Wo,
    const float* __restrict__ bo, float* __restrict__ outp,
    const float* __restrict__ avg, const float* __restrict__ fiber,
    float* __restrict__ fpre,
    const float* __restrict__ rowpart, float* __restrict__ totv)
{
    __shared__ float As[2][32][68];
    __shared__ float Bs[2][32][68];
    int x = blockIdx.x;
    if (x < 64) {
        int by = x >> 3, bx = x & 7;
        gemm_tile(outpre, Wo, bo, outp, 512, 512, 512, 512,
                  by * 64, bx * 64, As, Bs);
    } else if (x < 192) {
        int v = x - 64;
        int bz = v >> 6, r = v & 63;
        int by = r >> 4, bx = r & 15;
        gemm_tile(avg + (long)bz * 65536, fiber + (long)bz * 262144, nullptr,
                  fpre + (long)bz * 262144, 256, 256, 1024, 1024,
                  by * 64, bx * 64, As, Bs);
    } else {
        // total_hol reduction over rowpart[4096]
        int t = threadIdx.x, lane = t & 31, w = t >> 5;
        float s = 0.f;
#pragma unroll
        for (int q = 0; q < 16; q++) s += rowpart[t + 256 * q];
#pragma unroll
        for (int o = 16; o; o >>= 1) s += __shfl_xor_sync(0xffffffffu, s, o);
        float* red = &As[0][0][0];
        if (lane == 0) red[w] = s;
        __syncthreads();
        if (t == 0) {
            float tot = 0.f;
#pragma unroll
            for (int q = 0; q < 8; q++) tot += red[q];
            *totv = tot;
        }
    }
}

// ======= 10) Newton-Schulz polar (warp-per-matrix, R6 exact) ================
__global__ __launch_bounds__(128) void ns_kernel(
    const float* __restrict__ Fin, float* __restrict__ Fout)
{
    __shared__ float X[4][32][PAD], S[4][32][PAD];
    int t = threadIdx.x;
    int w = t >> 5, lane = t & 31;
    int rg = lane >> 2, cg = lane & 3;
    int zi = blockIdx.x * 4 + w;

    const float4* f4 = (const float4*)(Fin + (size_t)zi * 1024);
    float4 vals[8];
    float sq = 0.f;
#pragma unroll
    for (int q = 0; q < 8; q++) {
        float4 v = f4[q * 32 + lane];
        vals[q] = v;
        sq += v.x*v.x + v.y*v.y + v.z*v.z + v.w*v.w;
    }
#pragma unroll
    for (int o = 16; o; o >>= 1) sq += __shfl_xor_sync(0xffffffffu, sq, o);
    float scale = rsqrtf(fmaxf(sq, 1e-30f));
#pragma unroll
    for (int q = 0; q < 8; q++) {
        int fi = q * 32 + lane;
        float4 v = vals[q];
        v.x *= scale; v.y *= scale; v.z *= scale; v.w *= scale;
        *(float4*)&X[w][fi >> 3][(fi & 7) * 4] = v;
    }
    __syncwarp();

    for (int iter = 0; iter < 64; iter++) {
        unsigned long long acc[4][4] = {};
        wtile_tn(X[w], X[w], acc, rg, cg);

        bool bad = false;
#pragma unroll
        for (int d = 0; d < 4; d++) {
            int a = 4 * rg + d;
#pragma unroll
            for (int e = 0; e < 4; e++) {
                float2 f = upk2(acc[d][e]);
                int b0i = 8 * cg + 2 * e, b1i = b0i + 1;
                bad |= fabsf(f.x - ((a == b0i) ? 1.f : 0.f)) > 2e-5f;
                bad |= fabsf(f.y - ((a == b1i) ? 1.f : 0.f)) > 2e-5f;
            }
        }
        if (!__any_sync(0xffffffffu, bad)) break;

        wtile_store(S[w], acc, rg, cg);
        __syncwarp();

        unsigned long long acc2[4][4] = {};
        wtile_nn(X[w], S[w], acc2, rg, cg);
        float y[4][8];
#pragma unroll
        for (int d = 0; d < 4; d++) {
            int row = 4 * rg + d;
            float4 x0 = *(const float4*)&X[w][row][8 * cg];
            float4 x1 = *(const float4*)&X[w][row][8 * cg + 4];
            float2 p0 = upk2(acc2[d][0]);
            float2 p1 = upk2(acc2[d][1]);
            float2 p2 = upk2(acc2[d][2]);
            float2 p3 = upk2(acc2[d][3]);
            y[d][0] = 1.5f*x0.x - 0.5f*p0.x; y[d][1] = 1.5f*x0.y - 0.5f*p0.y;
            y[d][2] = 1.5f*x0.z - 0.5f*p1.x; y[d][3] = 1.5f*x0.w - 0.5f*p1.y;
            y[d][4] = 1.5f*x1.x - 0.5f*p2.x; y[d][5] = 1.5f*x1.y - 0.5f*p2.y;
            y[d][6] = 1.5f*x1.z - 0.5f*p3.x; y[d][7] = 1.5f*x1.w - 0.5f*p3.y;
        }
        __syncwarp();
#pragma unroll
        for (int d = 0; d < 4; d++) {
            int row = 4 * rg + d;
            *(float4*)&X[w][row][8 * cg]     = make_float4(y[d][0], y[d][1], y[d][2], y[d][3]);
            *(float4*)&X[w][row][8 * cg + 4] = make_float4(y[d][4], y[d][5], y[d][6], y[d][7]);
        }
        __syncwarp();
    }

    float* fo = Fout + (size_t)zi * 1024;
#pragma unroll
    for (int q = 0; q < 8; q++) {
        int fi = q * 32 + lane;
        float4 v = *(const float4*)&X[w][fi >> 3][(fi & 7) * 4];
        *(float4*)(fo + fi * 4) = v;
    }
}

// ======================= launcher ===========================================
extern "C" void kernel_launch(void* const* d_in, const int* in_sizes, int n_in,
                              void* d_out, int out_size)
{
    const float* base  = (const float*)d_in[0];
    const float* fiber = (const float*)d_in[1];
    const float* conn  = (const float*)d_in[2];
    const float* gen   = (const float*)d_in[3];
    const float* Wq    = (const float*)d_in[4];
    const float* bq    = (const float*)d_in[5];
    const float* Wk    = (const float*)d_in[6];
    const float* bk    = (const float*)d_in[7];
    const float* Wv    = (const float*)d_in[8];
    const float* bv    = (const float*)d_in[9];
    const float* Wo    = (const float*)d_in[10];
    const float* bo    = (const float*)d_in[11];
    const float* lam   = (const float*)d_in[12];
    float* out = (float*)d_out;

    float* sc;
    cudaGetSymbolAddress((void**)&sc, g_scratch);
    float* M       = sc;
    float* hol     = M + 524288;
    float* Q       = hol + 131072;
    float* Km      = Q + 262144;
    float* V       = Km + 262144;
    float* attn    = V + 262144;
    float* avg     = attn + 1048576;
    float* outpre  = avg + 131072;
    float* fpre    = outpre + 262144;
    float* rowpart = fpre + 524288;

    // 1) expm + M
    expm_kernel<<<256, 64>>>(conn, gen, M);

    // 2+3) QKV (192 blocks) fused with holonomy
    hol_qkv_kernel<<<192 + 8448, 256>>>(M, hol, base, Wq, Wk, Wv,
                                        bq, bk, bv, Q, Km, V);

    // 4) scores
    scores_kernel<<<dim3(4, 4, 16), 256>>>(Q, Km, hol, lam, attn);

    // 5) softmax (warp per row)
    softmax_kernel<<<512, 256>>>(attn, hol, rowpart);

    // 6+8) attn@V || head-average
    tail1_kernel<<<576, 256>>>(attn, V, outpre, avg);

    // 7+9+11) @Wo+bo || avg@fiber || total_hol
    tail2_kernel<<<193, 256>>>(outpre, Wo, bo, out, avg, fiber, fpre,
                               rowpart, out + 786432);

    // 10) polar projection (warp-autonomous NS)
    ns_kernel<<<128, 128>>>(fpre, out + 262144);
}